// round 1
// baseline (speedup 1.0000x reference)
#include <cuda_runtime.h>
#include <math.h>

#define NB 16384
#define ND_IN 512
#define NH 1024
#define NO 512
#define NE 8
#define NK 2

// output layout (fp32, flattened tuple)
#define RAW_OFF (NB * NO)                    // 8388608
#define IDX_OFF (RAW_OFF + NB * NE)          // 8519680
#define ENT_OFF (IDX_OFF + NB * NK)          // 8552448

// ----- scratch (__device__ globals; no allocations allowed) -----
__device__ int   g_counts[NE];
__device__ float g_entropy;
__device__ int   g_pair[NE * NB];   // pair = 2*b + slot, grouped per expert
__device__ float g_pw[NE * NB];     // combine weight per (token, slot)
__device__ float g_H[(size_t)NB * NK * NH];  // 128 MB
__device__ float g_Y[(size_t)NB * NK * NO];  // 64 MB

// ---------------------------------------------------------------
__global__ void zero_kernel() {
    int t = threadIdx.x;
    if (t < NE) g_counts[t] = 0;
    if (t == 0) g_entropy = 0.0f;
}

// ---------------------------------------------------------------
// Gating: one warp per token.
__global__ __launch_bounds__(256) void gate_kernel(
    const float* __restrict__ x, const float* __restrict__ gw,
    const float* __restrict__ gb, float* __restrict__ out)
{
    __shared__ float gws[NE * ND_IN];   // [e][d], transposed for conflict-free reads
    __shared__ float gbs[NE];
    __shared__ float s_ent[8];

    int tid = threadIdx.x;
    for (int i = tid; i < NE * ND_IN; i += blockDim.x) {
        int e = i >> 9;       // i / 512
        int d = i & 511;
        gws[i] = gw[d * NE + e];
    }
    if (tid < NE) gbs[tid] = gb[tid];
    __syncthreads();

    int warp = tid >> 5, lane = tid & 31;
    int b = blockIdx.x * 8 + warp;   // 2048 blocks * 8 warps = 16384

    float acc[NE];
#pragma unroll
    for (int e = 0; e < NE; e++) acc[e] = 0.0f;

    const float* xr = x + (size_t)b * ND_IN;
#pragma unroll 4
    for (int i = 0; i < 16; i++) {
        float xv = xr[lane + 32 * i];
#pragma unroll
        for (int e = 0; e < NE; e++)
            acc[e] += xv * gws[e * ND_IN + lane + 32 * i];
    }
#pragma unroll
    for (int e = 0; e < NE; e++) {
#pragma unroll
        for (int off = 16; off > 0; off >>= 1)
            acc[e] += __shfl_xor_sync(0xffffffffu, acc[e], off);
    }

    if (lane == 0) {
        float raw[NE];
        float m = -1e30f;
#pragma unroll
        for (int e = 0; e < NE; e++) { raw[e] = acc[e] + gbs[e]; m = fmaxf(m, raw[e]); }
        float p[NE];
        float s = 0.0f;
#pragma unroll
        for (int e = 0; e < NE; e++) { p[e] = expf(raw[e] - m); s += p[e]; }
        float inv = 1.0f / s;
        float ent = 0.0f;
#pragma unroll
        for (int e = 0; e < NE; e++) {
            p[e] *= inv;
            ent -= p[e] * logf(p[e] + 1e-9f);
            out[RAW_OFF + (size_t)b * NE + e] = raw[e];
        }
        // top-2, ties -> lower index first (jax.lax.top_k semantics)
        int i0 = 0;
#pragma unroll
        for (int e = 1; e < NE; e++) if (p[e] > p[i0]) i0 = e;
        int i1 = (i0 == 0) ? 1 : 0;
#pragma unroll
        for (int e = 0; e < NE; e++) if (e != i0 && e != i1 && p[e] > p[i1]) i1 = e;

        out[IDX_OFF + 2 * b + 0] = (float)i0;
        out[IDX_OFF + 2 * b + 1] = (float)i1;

        float v0 = p[i0], v1 = p[i1];
        float mm = fmaxf(v0, v1);
        float e0 = expf(v0 - mm), e1 = expf(v1 - mm);
        float iz = 1.0f / (e0 + e1);
        float w0 = e0 * iz, w1 = e1 * iz;

        int pos0 = atomicAdd(&g_counts[i0], 1);
        g_pair[i0 * NB + pos0] = 2 * b;
        g_pw[i0 * NB + pos0]   = w0;
        int pos1 = atomicAdd(&g_counts[i1], 1);
        g_pair[i1 * NB + pos1] = 2 * b + 1;
        g_pw[i1 * NB + pos1]   = w1;

        s_ent[warp] = ent;
    }
    __syncthreads();
    if (tid == 0) {
        float t = 0.0f;
#pragma unroll
        for (int w = 0; w < 8; w++) t += s_ent[w];
        atomicAdd(&g_entropy, t);
    }
}

// ---------------------------------------------------------------
// Grouped gather-GEMM. MODE 0: H = relu(x_gather @ W1_e + b1_e)
//                      MODE 1: Y = w * (H_gather @ W2_e + b2_e)
template<int KD, int NDIM, int MODE>
__global__ __launch_bounds__(256) void expert_gemm(
    const float* __restrict__ A, const float* __restrict__ Wfull,
    const float* __restrict__ bfull, float* __restrict__ Out)
{
    const int e = blockIdx.z;
    const int n_e = g_counts[e];
    const int m0 = blockIdx.y * 128;
    if (m0 >= n_e) return;
    const int n0 = blockIdx.x * 128;

    const float* W = Wfull + (size_t)e * KD * NDIM;
    const float* bias = bfull + (size_t)e * NDIM;

    __shared__ float As[8][128];
    __shared__ float Bs[8][128];
    __shared__ int   s_pair[128];
    __shared__ float s_w[128];

    const int tid = threadIdx.x;
    for (int r = tid; r < 128; r += 256) {
        int gi = m0 + r;
        if (gi < n_e) { s_pair[r] = g_pair[e * NB + gi]; s_w[r] = g_pw[e * NB + gi]; }
        else          { s_pair[r] = -1;                  s_w[r] = 0.0f; }
    }
    __syncthreads();

    const int ar = tid >> 1;           // 0..127 (A row within tile)
    const int ak = (tid & 1) * 4;      // k sub-offset 0 or 4
    const int bk = tid >> 5;           // 0..7
    const int bn = (tid & 31) * 4;

    int pr = s_pair[ar];
    int safep = (pr < 0) ? 0 : pr;
    const float* arow = (MODE == 0)
        ? A + (size_t)(safep >> 1) * ND_IN
        : A + (size_t)safep * NH;

    const int tx = tid & 15;    // col group
    const int ty = tid >> 4;    // row group

    float accv[8][8];
#pragma unroll
    for (int i = 0; i < 8; i++)
#pragma unroll
        for (int j = 0; j < 8; j++) accv[i][j] = 0.0f;

    for (int k0 = 0; k0 < KD; k0 += 8) {
        float4 av = *(const float4*)(arow + k0 + ak);
        float4 bv = *(const float4*)(W + (size_t)(k0 + bk) * NDIM + n0 + bn);
        As[ak + 0][ar] = av.x;
        As[ak + 1][ar] = av.y;
        As[ak + 2][ar] = av.z;
        As[ak + 3][ar] = av.w;
        *(float4*)&Bs[bk][bn] = bv;
        __syncthreads();

#pragma unroll
        for (int kk = 0; kk < 8; kk++) {
            float a[8], bb[8];
#pragma unroll
            for (int i = 0; i < 8; i++) a[i] = As[kk][ty * 8 + i];
#pragma unroll
            for (int j = 0; j < 8; j++) bb[j] = Bs[kk][tx * 8 + j];
#pragma unroll
            for (int i = 0; i < 8; i++)
#pragma unroll
                for (int j = 0; j < 8; j++)
                    accv[i][j] += a[i] * bb[j];
        }
        __syncthreads();
    }

    float bloc[8];
#pragma unroll
    for (int j = 0; j < 8; j++) bloc[j] = bias[n0 + tx * 8 + j];

#pragma unroll
    for (int i = 0; i < 8; i++) {
        int r = ty * 8 + i;
        int p = s_pair[r];
        if (p < 0) continue;
        float w = s_w[r];
        float vals[8];
#pragma unroll
        for (int j = 0; j < 8; j++) {
            float v = accv[i][j] + bloc[j];
            if (MODE == 0) v = fmaxf(v, 0.0f);
            else           v = w * v;
            vals[j] = v;
        }
        float* dst = Out + (size_t)p * NDIM + n0 + tx * 8;
        *(float4*)(dst + 0) = make_float4(vals[0], vals[1], vals[2], vals[3]);
        *(float4*)(dst + 4) = make_float4(vals[4], vals[5], vals[6], vals[7]);
    }
}

// ---------------------------------------------------------------
__global__ __launch_bounds__(256) void combine_kernel(float* __restrict__ out)
{
    const float4* Y4 = (const float4*)g_Y;
    float4* out4 = (float4*)out;
    int i4 = blockIdx.x * blockDim.x + threadIdx.x;   // 2097152 total
    int olin = i4 * 4;
    int b = olin >> 9;          // /512
    int o4 = (olin & 511) >> 2; // float4 within row
    float4 a = Y4[(size_t)b * 256 + o4];
    float4 c = Y4[(size_t)b * 256 + 128 + o4];
    out4[i4] = make_float4(a.x + c.x, a.y + c.y, a.z + c.z, a.w + c.w);
    if (i4 == 0) out[ENT_OFF] = g_entropy * (1.0f / (float)NB);
}

// ---------------------------------------------------------------
extern "C" void kernel_launch(void* const* d_in, const int* in_sizes, int n_in,
                              void* d_out, int out_size)
{
    const float* x  = (const float*)d_in[0];
    const float* gw = (const float*)d_in[1];
    const float* gb = (const float*)d_in[2];
    const float* w1 = (const float*)d_in[3];
    const float* b1 = (const float*)d_in[4];
    const float* w2 = (const float*)d_in[5];
    const float* b2 = (const float*)d_in[6];
    float* out = (float*)d_out;

    float* hbuf; cudaGetSymbolAddress((void**)&hbuf, g_H);
    float* ybuf; cudaGetSymbolAddress((void**)&ybuf, g_Y);

    zero_kernel<<<1, 32>>>();
    gate_kernel<<<NB / 8, 256>>>(x, gw, gb, out);

    // GEMM A: [n_e, 512] @ [512, 1024] -> relu -> g_H
    dim3 gridA(NH / 128, NB / 128, NE);
    expert_gemm<ND_IN, NH, 0><<<gridA, 256>>>(x, w1, b1, hbuf);

    // GEMM B: [n_e, 1024] @ [1024, 512] -> *w -> g_Y
    dim3 gridB(NO / 128, NB / 128, NE);
    expert_gemm<NH, NO, 1><<<gridB, 256>>>(hbuf, w2, b2, ybuf);

    combine_kernel<<<(NB * NO / 4) / 256, 256>>>(out);
}

// round 3
// speedup vs baseline: 2.3058x; 2.3058x over previous
#include <cuda_runtime.h>
#include <cuda_bf16.h>
#include <math.h>
#include <stdint.h>

#define NB 16384
#define ND_IN 512
#define NH 1024
#define NO 512
#define NE 8
#define NK 2

// output layout (fp32, flattened tuple)
#define RAW_OFF (NB * NO)
#define IDX_OFF (RAW_OFF + NB * NE)
#define ENT_OFF (IDX_OFF + NB * NK)

// ================= helpers =================
__device__ __forceinline__ uint32_t smem_to_u32(const void* p) {
    uint32_t a;
    asm("{ .reg .u64 t; cvta.to.shared.u64 t, %1; cvt.u32.u64 %0, t; }" : "=r"(a) : "l"(p));
    return a;
}
__device__ __forceinline__ void cp_async16(uint32_t dst, const void* src) {
    asm volatile("cp.async.cg.shared.global [%0], [%1], 16;" :: "r"(dst), "l"(src));
}
#define CP_COMMIT() asm volatile("cp.async.commit_group;" ::: "memory")
#define CP_WAIT1()  asm volatile("cp.async.wait_group 1;" ::: "memory")

__device__ __forceinline__ void ldmatrix4(uint32_t* r, uint32_t addr) {
    asm volatile("ldmatrix.sync.aligned.m8n8.x4.shared.b16 {%0,%1,%2,%3}, [%4];"
                 : "=r"(r[0]), "=r"(r[1]), "=r"(r[2]), "=r"(r[3]) : "r"(addr));
}
__device__ __forceinline__ void mma16816(float* c, const uint32_t* a, uint32_t b0, uint32_t b1) {
    asm volatile("mma.sync.aligned.m16n8k16.row.col.f32.bf16.bf16.f32 "
                 "{%0,%1,%2,%3}, {%4,%5,%6,%7}, {%8,%9}, {%0,%1,%2,%3};"
                 : "+f"(c[0]), "+f"(c[1]), "+f"(c[2]), "+f"(c[3])
                 : "r"(a[0]), "r"(a[1]), "r"(a[2]), "r"(a[3]), "r"(b0), "r"(b1));
}

// ================= scratch =================
__device__ int   g_counts[NE];
__device__ float g_entropy;
__device__ int   g_pair[NE * NB];
__device__ float g_pw[NE * NB];

__device__ __align__(16) __nv_bfloat16 g_xhi[(size_t)NB * ND_IN];
__device__ __align__(16) __nv_bfloat16 g_xlo[(size_t)NB * ND_IN];
__device__ __align__(16) __nv_bfloat16 g_w1hi[(size_t)NE * NH * ND_IN];   // [e][n][k]
__device__ __align__(16) __nv_bfloat16 g_w1lo[(size_t)NE * NH * ND_IN];
__device__ __align__(16) __nv_bfloat16 g_w2hi[(size_t)NE * NO * NH];      // [e][o][k]
__device__ __align__(16) __nv_bfloat16 g_w2lo[(size_t)NE * NO * NH];
__device__ __align__(16) __nv_bfloat16 g_Hhi[(size_t)NB * NK * NH];
__device__ __align__(16) __nv_bfloat16 g_Hlo[(size_t)NB * NK * NH];
__device__ __align__(16) float g_Y[(size_t)NB * NK * NO];

// ================= small kernels =================
__global__ void zero_kernel() {
    int t = threadIdx.x;
    if (t < NE) g_counts[t] = 0;
    if (t == 0) g_entropy = 0.0f;
}

__device__ __forceinline__ void split1(float v, __nv_bfloat16& hi, __nv_bfloat16& lo) {
    hi = __float2bfloat16_rn(v);
    lo = __float2bfloat16_rn(v - __bfloat162float(hi));
}

__global__ __launch_bounds__(256) void convert_x_kernel(const float* __restrict__ x) {
    size_t i4 = (size_t)blockIdx.x * blockDim.x + threadIdx.x;
    float4 v = ((const float4*)x)[i4];
    __nv_bfloat16 h[4], l[4];
    split1(v.x, h[0], l[0]); split1(v.y, h[1], l[1]);
    split1(v.z, h[2], l[2]); split1(v.w, h[3], l[3]);
    ((uint2*)g_xhi)[i4] = *(uint2*)h;
    ((uint2*)g_xlo)[i4] = *(uint2*)l;
}

// transpose + split: w[e][k][n] -> out[e][n][k]
template<int KD, int ND>
__global__ __launch_bounds__(256) void convert_w_kernel(
    const float* __restrict__ w, __nv_bfloat16* __restrict__ whi, __nv_bfloat16* __restrict__ wlo)
{
    __shared__ float tile[32][33];
    int e = blockIdx.z;
    int n0 = blockIdx.x * 32;
    int k0 = blockIdx.y * 32;
    int tx = threadIdx.x & 31, ty = threadIdx.x >> 5;
    const float* we = w + (size_t)e * KD * ND;
#pragma unroll
    for (int ii = 0; ii < 4; ii++) {
        int k = ty + ii * 8;
        tile[k][tx] = we[(size_t)(k0 + k) * ND + n0 + tx];
    }
    __syncthreads();
#pragma unroll
    for (int ii = 0; ii < 4; ii++) {
        int n = ty + ii * 8;
        float v = tile[tx][n];
        __nv_bfloat16 h, l;
        split1(v, h, l);
        size_t o = ((size_t)e * ND + n0 + n) * KD + k0 + tx;
        whi[o] = h; wlo[o] = l;
    }
}

// ================= gating =================
__global__ __launch_bounds__(256) void gate_kernel(
    const float* __restrict__ x, const float* __restrict__ gw,
    const float* __restrict__ gb, float* __restrict__ out)
{
    __shared__ float gws[NE * ND_IN];
    __shared__ float gbs[NE];
    __shared__ float s_ent[8];

    int tid = threadIdx.x;
    for (int i = tid; i < NE * ND_IN; i += blockDim.x) {
        int e = i >> 9;
        int d = i & 511;
        gws[i] = gw[d * NE + e];
    }
    if (tid < NE) gbs[tid] = gb[tid];
    __syncthreads();

    int warp = tid >> 5, lane = tid & 31;
    int b = blockIdx.x * 8 + warp;

    float acc[NE];
#pragma unroll
    for (int e = 0; e < NE; e++) acc[e] = 0.0f;
    const float* xr = x + (size_t)b * ND_IN;
#pragma unroll 4
    for (int i = 0; i < 16; i++) {
        float xv = xr[lane + 32 * i];
#pragma unroll
        for (int e = 0; e < NE; e++) acc[e] += xv * gws[e * ND_IN + lane + 32 * i];
    }
#pragma unroll
    for (int e = 0; e < NE; e++) {
#pragma unroll
        for (int off = 16; off > 0; off >>= 1)
            acc[e] += __shfl_xor_sync(0xffffffffu, acc[e], off);
    }

    if (lane == 0) {
        float raw[NE];
        float m = -1e30f;
#pragma unroll
        for (int e = 0; e < NE; e++) { raw[e] = acc[e] + gbs[e]; m = fmaxf(m, raw[e]); }
        float p[NE];
        float s = 0.0f;
#pragma unroll
        for (int e = 0; e < NE; e++) { p[e] = expf(raw[e] - m); s += p[e]; }
        float inv = 1.0f / s;
        float ent = 0.0f;
#pragma unroll
        for (int e = 0; e < NE; e++) {
            p[e] *= inv;
            ent -= p[e] * logf(p[e] + 1e-9f);
            out[RAW_OFF + (size_t)b * NE + e] = raw[e];
        }
        int i0 = 0;
#pragma unroll
        for (int e = 1; e < NE; e++) if (p[e] > p[i0]) i0 = e;
        int i1 = (i0 == 0) ? 1 : 0;
#pragma unroll
        for (int e = 0; e < NE; e++) if (e != i0 && e != i1 && p[e] > p[i1]) i1 = e;

        out[IDX_OFF + 2 * b + 0] = (float)i0;
        out[IDX_OFF + 2 * b + 1] = (float)i1;

        float v0 = p[i0], v1 = p[i1];
        float mm = fmaxf(v0, v1);
        float e0 = expf(v0 - mm), e1 = expf(v1 - mm);
        float iz = 1.0f / (e0 + e1);

        int pos0 = atomicAdd(&g_counts[i0], 1);
        g_pair[i0 * NB + pos0] = 2 * b;
        g_pw[i0 * NB + pos0]   = e0 * iz;
        int pos1 = atomicAdd(&g_counts[i1], 1);
        g_pair[i1 * NB + pos1] = 2 * b + 1;
        g_pw[i1 * NB + pos1]   = e1 * iz;

        s_ent[warp] = ent;
    }
    __syncthreads();
    if (tid == 0) {
        float t = 0.0f;
#pragma unroll
        for (int w = 0; w < 8; w++) t += s_ent[w];
        atomicAdd(&g_entropy, t);
    }
}

// ================= HMMA grouped gather GEMM =================
// MODE 0: H(bf16 hi/lo) = relu(x gather @ w1 + b1)   KD=512,  NDIM=1024
// MODE 1: Y(f32)        = w * (H gather @ w2 + b2)   KD=1024, NDIM=512
// Virtual K = 3*KD: segment 0: Ahi*Whi, 1: Ahi*Wlo, 2: Alo*Whi.
// CTA 128x128, BK=32 bf16 (64B), smem rows padded to 80B, 3-stage cp.async.

#define APITCH 80
#define TILE_BYTES (128 * APITCH)          // 10240
#define STAGE_BYTES (2 * TILE_BYTES)       // 20480
#define HDR_BYTES 2048
#define SMEM_TOT (HDR_BYTES + 3 * STAGE_BYTES)   // 63488

template<int KD, int MODE>
__global__ __launch_bounds__(256, 2) void expert_gemm_mma(const float* __restrict__ bias_full)
{
    constexpr int NDIM = (MODE == 0) ? NH : NO;
    constexpr int RS   = (MODE == 0) ? ND_IN : NH;
    constexpr int KC   = KD / 32;       // chunks per segment
    constexpr int NIT  = 3 * KC;

    extern __shared__ char smem[];
    int*   s_pair = (int*)smem;
    float* s_w    = (float*)(smem + 512);
    float* s_bias = (float*)(smem + 1024);
    const uint32_t tilesU = smem_to_u32(smem + HDR_BYTES);

    const int e = blockIdx.z;
    const int n_e = g_counts[e];
    const int m0 = blockIdx.y * 128;
    if (m0 >= n_e) return;
    const int n0 = blockIdx.x * 128;
    const int tid = threadIdx.x;
    const int lane = tid & 31, wid = tid >> 5;

    if (tid < 128) {
        int gi = m0 + tid;
        if (gi < n_e) { s_pair[tid] = g_pair[e * NB + gi]; s_w[tid] = g_pw[e * NB + gi]; }
        else          { s_pair[tid] = -1;                  s_w[tid] = 0.0f; }
        s_bias[tid] = bias_full[(size_t)e * NDIM + n0 + tid];
    }
    __syncthreads();

    const __nv_bfloat16* Ahi = (MODE == 0) ? g_xhi : g_Hhi;
    const __nv_bfloat16* Alo = (MODE == 0) ? g_xlo : g_Hlo;
    const __nv_bfloat16* Whi = ((MODE == 0) ? g_w1hi : g_w2hi) + (size_t)e * NDIM * KD;
    const __nv_bfloat16* Wlo = ((MODE == 0) ? g_w1lo : g_w2lo) + (size_t)e * NDIM * KD;

    // per-thread load slots: rows lr0 and lr0+64, 16B part
    const int lr0 = tid >> 2;
    const int lr1 = lr0 + 64;
    const int part = tid & 3;

    int pp0 = s_pair[lr0], pp1 = s_pair[lr1];
    const size_t ar0 = (size_t)((pp0 < 0) ? 0 : ((MODE == 0) ? (pp0 >> 1) : pp0));
    const size_t ar1 = (size_t)((pp1 < 0) ? 0 : ((MODE == 0) ? (pp1 >> 1) : pp1));
    const size_t aoff0 = ar0 * RS * 2 + part * 16;
    const size_t aoff1 = ar1 * RS * 2 + part * 16;
    const size_t boff0 = (size_t)(n0 + lr0) * KD * 2 + part * 16;
    const size_t boff1 = (size_t)(n0 + lr1) * KD * 2 + part * 16;

    const uint32_t dA0 = lr0 * APITCH + part * 16;
    const uint32_t dA1 = lr1 * APITCH + part * 16;
    const uint32_t dB0 = TILE_BYTES + lr0 * APITCH + part * 16;
    const uint32_t dB1 = TILE_BYTES + lr1 * APITCH + part * 16;

    auto load_stage = [&](int it) {
        const int seg = it / KC;
        const int kc  = it - seg * KC;
        const char* pa = (const char*)((seg < 2) ? Ahi : Alo) + (size_t)kc * 64;
        const char* pb = (const char*)((seg == 1) ? Wlo : Whi) + (size_t)kc * 64;
        const uint32_t db = tilesU + (uint32_t)(it % 3) * STAGE_BYTES;
        cp_async16(db + dA0, pa + aoff0);
        cp_async16(db + dA1, pa + aoff1);
        cp_async16(db + dB0, pb + boff0);
        cp_async16(db + dB1, pb + boff1);
    };

    float acc[2][8][4];
#pragma unroll
    for (int mi = 0; mi < 2; mi++)
#pragma unroll
        for (int ni = 0; ni < 8; ni++)
#pragma unroll
            for (int q = 0; q < 4; q++) acc[mi][ni][q] = 0.0f;

    const int wm0 = (wid & 3) * 32;
    const int wn0 = (wid >> 2) * 64;

    // ldmatrix lane addressing (row, 16B-chunk) bases
    const int aRowLane = (lane & 15);
    const int aChkLane = (lane >> 4);
    const int bRowLane = ((lane >> 4) << 3) + (lane & 7);
    const int bChkLane = ((lane >> 3) & 1);

    load_stage(0); CP_COMMIT();
    load_stage(1); CP_COMMIT();

    for (int it = 0; it < NIT; it++) {
        CP_WAIT1();
        __syncthreads();
        if (it + 2 < NIT) load_stage(it + 2);
        CP_COMMIT();

        const uint32_t aBase = tilesU + (uint32_t)(it % 3) * STAGE_BYTES;
        const uint32_t bBase = aBase + TILE_BYTES;

#pragma unroll
        for (int s = 0; s < 2; s++) {
            uint32_t a[2][4];
#pragma unroll
            for (int mi = 0; mi < 2; mi++) {
                uint32_t addr = aBase + (uint32_t)(wm0 + mi * 16 + aRowLane) * APITCH
                              + (uint32_t)(2 * s + aChkLane) * 16;
                ldmatrix4(a[mi], addr);
            }
#pragma unroll
            for (int nq = 0; nq < 4; nq++) {
                uint32_t b[4];
                uint32_t addr = bBase + (uint32_t)(wn0 + nq * 16 + bRowLane) * APITCH
                              + (uint32_t)(2 * s + bChkLane) * 16;
                ldmatrix4(b, addr);
#pragma unroll
                for (int mi = 0; mi < 2; mi++) {
                    mma16816(acc[mi][2 * nq],     a[mi], b[0], b[1]);
                    mma16816(acc[mi][2 * nq + 1], a[mi], b[2], b[3]);
                }
            }
        }
    }

    // ================= epilogue =================
#pragma unroll
    for (int mi = 0; mi < 2; mi++) {
#pragma unroll
        for (int half = 0; half < 2; half++) {
            const int rloc = wm0 + mi * 16 + (lane >> 2) + half * 8;
            const int p = s_pair[rloc];
            if (p < 0) continue;
            const float wt = s_w[rloc];
#pragma unroll
            for (int ni = 0; ni < 8; ni++) {
                const int col = wn0 + ni * 8 + 2 * (lane & 3);
                float v0 = acc[mi][ni][2 * half]     + s_bias[col];
                float v1 = acc[mi][ni][2 * half + 1] + s_bias[col + 1];
                if (MODE == 0) {
                    v0 = fmaxf(v0, 0.0f);
                    v1 = fmaxf(v1, 0.0f);
                    __nv_bfloat162 h = __floats2bfloat162_rn(v0, v1);
                    float r0 = v0 - __bfloat162float(h.x);
                    float r1 = v1 - __bfloat162float(h.y);
                    __nv_bfloat162 l = __floats2bfloat162_rn(r0, r1);
                    *(__nv_bfloat162*)(g_Hhi + (size_t)p * NH + n0 + col) = h;
                    *(__nv_bfloat162*)(g_Hlo + (size_t)p * NH + n0 + col) = l;
                } else {
                    float2 o = make_float2(v0 * wt, v1 * wt);
                    *(float2*)(g_Y + (size_t)p * NO + n0 + col) = o;
                }
            }
        }
    }
}

// ================= combine =================
__global__ __launch_bounds__(256) void combine_kernel(float* __restrict__ out)
{
    const float4* Y4 = (const float4*)g_Y;
    float4* out4 = (float4*)out;
    int i4 = blockIdx.x * blockDim.x + threadIdx.x;
    int olin = i4 * 4;
    int b = olin >> 9;
    int o4 = (olin & 511) >> 2;
    float4 a = Y4[(size_t)b * 256 + o4];
    float4 c = Y4[(size_t)b * 256 + 128 + o4];
    out4[i4] = make_float4(a.x + c.x, a.y + c.y, a.z + c.z, a.w + c.w);
    if (i4 == 0) out[ENT_OFF] = g_entropy * (1.0f / (float)NB);
}

// ================= host =================
extern "C" void kernel_launch(void* const* d_in, const int* in_sizes, int n_in,
                              void* d_out, int out_size)
{
    const float* x  = (const float*)d_in[0];
    const float* gw = (const float*)d_in[1];
    const float* gb = (const float*)d_in[2];
    const float* w1 = (const float*)d_in[3];
    const float* b1 = (const float*)d_in[4];
    const float* w2 = (const float*)d_in[5];
    const float* b2 = (const float*)d_in[6];
    float* out = (float*)d_out;

    __nv_bfloat16 *w1h, *w1l, *w2h, *w2l;
    cudaGetSymbolAddress((void**)&w1h, g_w1hi);
    cudaGetSymbolAddress((void**)&w1l, g_w1lo);
    cudaGetSymbolAddress((void**)&w2h, g_w2hi);
    cudaGetSymbolAddress((void**)&w2l, g_w2lo);

    cudaFuncSetAttribute(expert_gemm_mma<ND_IN, 0>, cudaFuncAttributeMaxDynamicSharedMemorySize, SMEM_TOT);
    cudaFuncSetAttribute(expert_gemm_mma<NH, 1>,    cudaFuncAttributeMaxDynamicSharedMemorySize, SMEM_TOT);

    zero_kernel<<<1, 32>>>();
    gate_kernel<<<NB / 8, 256>>>(x, gw, gb, out);

    convert_x_kernel<<<(NB * ND_IN / 4) / 256, 256>>>(x);
    convert_w_kernel<ND_IN, NH><<<dim3(NH / 32, ND_IN / 32, NE), 256>>>(w1, w1h, w1l);
    convert_w_kernel<NH, NO><<<dim3(NO / 32, NH / 32, NE), 256>>>(w2, w2h, w2l);

    expert_gemm_mma<ND_IN, 0><<<dim3(NH / 128, 128, NE), 256, SMEM_TOT>>>(b1);
    expert_gemm_mma<NH, 1><<<dim3(NO / 128, 128, NE), 256, SMEM_TOT>>>(b2);

    combine_kernel<<<(NB * NO / 4) / 256, 256>>>(out);
}

// round 4
// speedup vs baseline: 2.4280x; 1.0530x over previous
#include <cuda_runtime.h>
#include <cuda_bf16.h>
#include <cuda_fp16.h>
#include <math.h>
#include <stdint.h>

#define NB 16384
#define ND_IN 512
#define NH 1024
#define NO 512
#define NE 8
#define NK 2

// output layout (fp32, flattened tuple)
#define RAW_OFF (NB * NO)
#define IDX_OFF (RAW_OFF + NB * NE)
#define ENT_OFF (IDX_OFF + NB * NK)

// ================= helpers =================
__device__ __forceinline__ uint32_t smem_to_u32(const void* p) {
    uint32_t a;
    asm("{ .reg .u64 t; cvta.to.shared.u64 t, %1; cvt.u32.u64 %0, t; }" : "=r"(a) : "l"(p));
    return a;
}
__device__ __forceinline__ void cp_async16(uint32_t dst, const void* src) {
    asm volatile("cp.async.cg.shared.global [%0], [%1], 16;" :: "r"(dst), "l"(src));
}
#define CP_COMMIT() asm volatile("cp.async.commit_group;" ::: "memory")
#define CP_WAIT1()  asm volatile("cp.async.wait_group 1;" ::: "memory")

__device__ __forceinline__ void ldmatrix4(uint32_t* r, uint32_t addr) {
    asm volatile("ldmatrix.sync.aligned.m8n8.x4.shared.b16 {%0,%1,%2,%3}, [%4];"
                 : "=r"(r[0]), "=r"(r[1]), "=r"(r[2]), "=r"(r[3]) : "r"(addr));
}
__device__ __forceinline__ void mma16816(float* c, const uint32_t* a, uint32_t b0, uint32_t b1) {
    asm volatile("mma.sync.aligned.m16n8k16.row.col.f32.f16.f16.f32 "
                 "{%0,%1,%2,%3}, {%4,%5,%6,%7}, {%8,%9}, {%0,%1,%2,%3};"
                 : "+f"(c[0]), "+f"(c[1]), "+f"(c[2]), "+f"(c[3])
                 : "r"(a[0]), "r"(a[1]), "r"(a[2]), "r"(a[3]), "r"(b0), "r"(b1));
}

// ================= scratch =================
__device__ int   g_counts[NE];
__device__ float g_entropy;
__device__ int   g_pair[NE * NB];
__device__ float g_pw[NE * NB];

__device__ __align__(16) __half g_xh[(size_t)NB * ND_IN];
__device__ __align__(16) __half g_xl[(size_t)NB * ND_IN];
__device__ __align__(16) __half g_w1h[(size_t)NE * NH * ND_IN];   // [e][n][k]
__device__ __align__(16) __half g_w2h[(size_t)NE * NO * NH];      // [e][o][k]
__device__ __align__(16) __half g_Hh[(size_t)NB * NK * NH];
__device__ __align__(16) __half g_Hl[(size_t)NB * NK * NH];
__device__ __align__(16) float  g_Y[(size_t)NB * NK * NO];

// ================= small kernels =================
__global__ void zero_kernel() {
    int t = threadIdx.x;
    if (t < NE) g_counts[t] = 0;
    if (t == 0) g_entropy = 0.0f;
}

// transpose + round: w[e][k][n] -> wh[e][n][k] (fp16)
template<int KD, int ND>
__global__ __launch_bounds__(256) void convert_w_kernel(
    const float* __restrict__ w, __half* __restrict__ wh)
{
    __shared__ float tile[32][33];
    int e = blockIdx.z;
    int n0 = blockIdx.x * 32;
    int k0 = blockIdx.y * 32;
    int tx = threadIdx.x & 31, ty = threadIdx.x >> 5;
    const float* we = w + (size_t)e * KD * ND;
#pragma unroll
    for (int ii = 0; ii < 4; ii++) {
        int k = ty + ii * 8;
        tile[k][tx] = we[(size_t)(k0 + k) * ND + n0 + tx];
    }
    __syncthreads();
#pragma unroll
    for (int ii = 0; ii < 4; ii++) {
        int n = ty + ii * 8;
        wh[((size_t)e * ND + n0 + n) * KD + k0 + tx] = __float2half_rn(tile[tx][n]);
    }
}

// ================= gating (+ fused x split) =================
__global__ __launch_bounds__(256) void gate_kernel(
    const float* __restrict__ x, const float* __restrict__ gw,
    const float* __restrict__ gb, float* __restrict__ out)
{
    __shared__ float gws[NE * ND_IN];
    __shared__ float gbs[NE];
    __shared__ float s_ent[8];

    int tid = threadIdx.x;
    for (int i = tid; i < NE * ND_IN; i += blockDim.x) {
        int e = i >> 9;
        int d = i & 511;
        gws[i] = gw[d * NE + e];
    }
    if (tid < NE) gbs[tid] = gb[tid];
    __syncthreads();

    int warp = tid >> 5, lane = tid & 31;
    int b = blockIdx.x * 8 + warp;

    float acc[NE];
#pragma unroll
    for (int e = 0; e < NE; e++) acc[e] = 0.0f;
    const float* xr = x + (size_t)b * ND_IN;
#pragma unroll 4
    for (int i = 0; i < 16; i++) {
        float xv = xr[lane + 32 * i];
        // fused x split (fp16 hi/lo)
        __half h = __float2half_rn(xv);
        __half l = __float2half_rn(xv - __half2float(h));
        g_xh[(size_t)b * ND_IN + lane + 32 * i] = h;
        g_xl[(size_t)b * ND_IN + lane + 32 * i] = l;
#pragma unroll
        for (int e = 0; e < NE; e++) acc[e] += xv * gws[e * ND_IN + lane + 32 * i];
    }
#pragma unroll
    for (int e = 0; e < NE; e++) {
#pragma unroll
        for (int off = 16; off > 0; off >>= 1)
            acc[e] += __shfl_xor_sync(0xffffffffu, acc[e], off);
    }

    if (lane == 0) {
        float raw[NE];
        float m = -1e30f;
#pragma unroll
        for (int e = 0; e < NE; e++) { raw[e] = acc[e] + gbs[e]; m = fmaxf(m, raw[e]); }
        float p[NE];
        float s = 0.0f;
#pragma unroll
        for (int e = 0; e < NE; e++) { p[e] = expf(raw[e] - m); s += p[e]; }
        float inv = 1.0f / s;
        float ent = 0.0f;
#pragma unroll
        for (int e = 0; e < NE; e++) {
            p[e] *= inv;
            ent -= p[e] * logf(p[e] + 1e-9f);
            out[RAW_OFF + (size_t)b * NE + e] = raw[e];
        }
        int i0 = 0;
#pragma unroll
        for (int e = 1; e < NE; e++) if (p[e] > p[i0]) i0 = e;
        int i1 = (i0 == 0) ? 1 : 0;
#pragma unroll
        for (int e = 0; e < NE; e++) if (e != i0 && e != i1 && p[e] > p[i1]) i1 = e;

        out[IDX_OFF + 2 * b + 0] = (float)i0;
        out[IDX_OFF + 2 * b + 1] = (float)i1;

        float v0 = p[i0], v1 = p[i1];
        float mm = fmaxf(v0, v1);
        float e0 = expf(v0 - mm), e1 = expf(v1 - mm);
        float iz = 1.0f / (e0 + e1);

        int pos0 = atomicAdd(&g_counts[i0], 1);
        g_pair[i0 * NB + pos0] = 2 * b;
        g_pw[i0 * NB + pos0]   = e0 * iz;
        int pos1 = atomicAdd(&g_counts[i1], 1);
        g_pair[i1 * NB + pos1] = 2 * b + 1;
        g_pw[i1 * NB + pos1]   = e1 * iz;

        s_ent[warp] = ent;
    }
    __syncthreads();
    if (tid == 0) {
        float t = 0.0f;
#pragma unroll
        for (int w = 0; w < 8; w++) t += s_ent[w];
        atomicAdd(&g_entropy, t);
    }
}

// ================= HMMA grouped gather GEMM =================
// 2-pass fp16 split of A; W rounded once. acc = A_hi@W + A_lo@W.
// MODE 0: H(fp16 hi/lo) = relu(x gather @ w1 + b1)   KD=512,  NDIM=1024
// MODE 1: Y(f32)        = w * (H gather @ w2 + b2)   KD=1024, NDIM=512
// CTA 128x128, 4 warps (warp tile 64x64), BK=32, 3-stage cp.async.

#define APITCH 80
#define TILE_BYTES (128 * APITCH)          // 10240  (one of Ah / Al / B)
#define STAGE_BYTES (3 * TILE_BYTES)       // 30720
#define HDR_BYTES 2048
#define SMEM_TOT (HDR_BYTES + 3 * STAGE_BYTES)   // 94208

template<int KD, int MODE>
__global__ __launch_bounds__(128, 2) void expert_gemm_mma(const float* __restrict__ bias_full)
{
    constexpr int NDIM = (MODE == 0) ? NH : NO;
    constexpr int RS   = (MODE == 0) ? ND_IN : NH;
    constexpr int NIT  = KD / 32;

    extern __shared__ char smem[];
    int*   s_pair = (int*)smem;
    float* s_w    = (float*)(smem + 512);
    float* s_bias = (float*)(smem + 1024);
    const uint32_t tilesU = smem_to_u32(smem + HDR_BYTES);

    const int e = blockIdx.z;
    const int n_e = g_counts[e];
    const int m0 = blockIdx.y * 128;
    if (m0 >= n_e) return;
    const int n0 = blockIdx.x * 128;
    const int tid = threadIdx.x;
    const int lane = tid & 31, wid = tid >> 5;

    {
        int gi = m0 + tid;
        if (gi < n_e) { s_pair[tid] = g_pair[e * NB + gi]; s_w[tid] = g_pw[e * NB + gi]; }
        else          { s_pair[tid] = -1;                  s_w[tid] = 0.0f; }
        s_bias[tid] = bias_full[(size_t)e * NDIM + n0 + tid];
    }
    __syncthreads();

    const __half* Ahp = (MODE == 0) ? g_xh : g_Hh;
    const __half* Alp = (MODE == 0) ? g_xl : g_Hl;
    const __half* Wp  = ((MODE == 0) ? g_w1h : g_w2h) + (size_t)e * NDIM * KD;

    // per-thread load row
    const int pp = s_pair[tid];
    const size_t arow = (size_t)((pp < 0) ? 0 : ((MODE == 0) ? (pp >> 1) : pp));
    const char* aH = (const char*)(Ahp + arow * RS);
    const char* aL = (const char*)(Alp + arow * RS);
    const char* bW = (const char*)(Wp + (size_t)(n0 + tid) * KD);
    const uint32_t rowDst = (uint32_t)tid * APITCH;

    auto load_stage = [&](int it) {
        const uint32_t db = tilesU + (uint32_t)(it % 3) * STAGE_BYTES;
        const size_t ko = (size_t)it * 64;
#pragma unroll
        for (int j = 0; j < 4; j++) {
            cp_async16(db + rowDst + j * 16,                  aH + ko + j * 16);
            cp_async16(db + TILE_BYTES + rowDst + j * 16,     aL + ko + j * 16);
            cp_async16(db + 2 * TILE_BYTES + rowDst + j * 16, bW + ko + j * 16);
        }
    };

    float acc[4][8][4];
#pragma unroll
    for (int mi = 0; mi < 4; mi++)
#pragma unroll
        for (int ni = 0; ni < 8; ni++)
#pragma unroll
            for (int q = 0; q < 4; q++) acc[mi][ni][q] = 0.0f;

    const int wm0 = (wid & 1) * 64;
    const int wn0 = (wid >> 1) * 64;
    const int aRow = (lane & 15);
    const int aChk = (lane >> 4);
    const int bRow = ((lane >> 4) << 3) + (lane & 7);
    const int bChk = ((lane >> 3) & 1);

    load_stage(0); CP_COMMIT();
    load_stage(1); CP_COMMIT();

    for (int it = 0; it < NIT; it++) {
        CP_WAIT1();
        __syncthreads();
        if (it + 2 < NIT) load_stage(it + 2);
        CP_COMMIT();

        const uint32_t st = tilesU + (uint32_t)(it % 3) * STAGE_BYTES;
#pragma unroll
        for (int s = 0; s < 2; s++) {
            uint32_t b[4][4];
#pragma unroll
            for (int q = 0; q < 4; q++)
                ldmatrix4(b[q], st + 2 * TILE_BYTES
                          + (uint32_t)(wn0 + q * 16 + bRow) * APITCH + (2 * s + bChk) * 16);
            uint32_t a[4][4];
#pragma unroll
            for (int mi = 0; mi < 4; mi++)
                ldmatrix4(a[mi], st
                          + (uint32_t)(wm0 + mi * 16 + aRow) * APITCH + (2 * s + aChk) * 16);
#pragma unroll
            for (int mi = 0; mi < 4; mi++)
#pragma unroll
                for (int q = 0; q < 4; q++) {
                    mma16816(acc[mi][2 * q],     a[mi], b[q][0], b[q][1]);
                    mma16816(acc[mi][2 * q + 1], a[mi], b[q][2], b[q][3]);
                }
#pragma unroll
            for (int mi = 0; mi < 4; mi++)
                ldmatrix4(a[mi], st + TILE_BYTES
                          + (uint32_t)(wm0 + mi * 16 + aRow) * APITCH + (2 * s + aChk) * 16);
#pragma unroll
            for (int mi = 0; mi < 4; mi++)
#pragma unroll
                for (int q = 0; q < 4; q++) {
                    mma16816(acc[mi][2 * q],     a[mi], b[q][0], b[q][1]);
                    mma16816(acc[mi][2 * q + 1], a[mi], b[q][2], b[q][3]);
                }
        }
    }

    // ================= epilogue =================
#pragma unroll
    for (int mi = 0; mi < 4; mi++) {
#pragma unroll
        for (int half = 0; half < 2; half++) {
            const int rloc = wm0 + mi * 16 + (lane >> 2) + half * 8;
            const int p = s_pair[rloc];
            if (p < 0) continue;
            const float wt = s_w[rloc];
#pragma unroll
            for (int ni = 0; ni < 8; ni++) {
                const int col = wn0 + ni * 8 + 2 * (lane & 3);
                float v0 = acc[mi][ni][2 * half]     + s_bias[col];
                float v1 = acc[mi][ni][2 * half + 1] + s_bias[col + 1];
                if (MODE == 0) {
                    v0 = fmaxf(v0, 0.0f);
                    v1 = fmaxf(v1, 0.0f);
                    __half2 h = __floats2half2_rn(v0, v1);
                    float r0 = v0 - __half2float(h.x);
                    float r1 = v1 - __half2float(h.y);
                    __half2 l = __floats2half2_rn(r0, r1);
                    *(__half2*)(g_Hh + (size_t)p * NH + n0 + col) = h;
                    *(__half2*)(g_Hl + (size_t)p * NH + n0 + col) = l;
                } else {
                    *(float2*)(g_Y + (size_t)p * NO + n0 + col) = make_float2(v0 * wt, v1 * wt);
                }
            }
        }
    }
}

// ================= combine =================
__global__ __launch_bounds__(256) void combine_kernel(float* __restrict__ out)
{
    const float4* Y4 = (const float4*)g_Y;
    float4* out4 = (float4*)out;
    int i4 = blockIdx.x * blockDim.x + threadIdx.x;
    int olin = i4 * 4;
    int b = olin >> 9;
    int o4 = (olin & 511) >> 2;
    float4 a = Y4[(size_t)b * 256 + o4];
    float4 c = Y4[(size_t)b * 256 + 128 + o4];
    out4[i4] = make_float4(a.x + c.x, a.y + c.y, a.z + c.z, a.w + c.w);
    if (i4 == 0) out[ENT_OFF] = g_entropy * (1.0f / (float)NB);
}

// ================= host =================
extern "C" void kernel_launch(void* const* d_in, const int* in_sizes, int n_in,
                              void* d_out, int out_size)
{
    const float* x  = (const float*)d_in[0];
    const float* gw = (const float*)d_in[1];
    const float* gb = (const float*)d_in[2];
    const float* w1 = (const float*)d_in[3];
    const float* b1 = (const float*)d_in[4];
    const float* w2 = (const float*)d_in[5];
    const float* b2 = (const float*)d_in[6];
    float* out = (float*)d_out;

    __half *w1h, *w2h;
    cudaGetSymbolAddress((void**)&w1h, g_w1h);
    cudaGetSymbolAddress((void**)&w2h, g_w2h);

    cudaFuncSetAttribute(expert_gemm_mma<ND_IN, 0>, cudaFuncAttributeMaxDynamicSharedMemorySize, SMEM_TOT);
    cudaFuncSetAttribute(expert_gemm_mma<NH, 1>,    cudaFuncAttributeMaxDynamicSharedMemorySize, SMEM_TOT);

    // order chosen so launch idx 3 = gemmA, idx 5 = gemmB (single-launch ncu capture)
    zero_kernel<<<1, 32>>>();                                                   // 0
    gate_kernel<<<NB / 8, 256>>>(x, gw, gb, out);                               // 1
    convert_w_kernel<ND_IN, NH><<<dim3(NH / 32, ND_IN / 32, NE), 256>>>(w1, w1h); // 2
    expert_gemm_mma<ND_IN, 0><<<dim3(NH / 128, 128, NE), 128, SMEM_TOT>>>(b1);  // 3
    convert_w_kernel<NH, NO><<<dim3(NO / 32, NH / 32, NE), 256>>>(w2, w2h);     // 4
    expert_gemm_mma<NH, 1><<<dim3(NO / 128, 128, NE), 128, SMEM_TOT>>>(b2);     // 5
    combine_kernel<<<(NB * NO / 4) / 256, 256>>>(out);                          // 6
}

// round 5
// speedup vs baseline: 3.0318x; 1.2487x over previous
#include <cuda_runtime.h>
#include <cuda_bf16.h>
#include <cuda_fp16.h>
#include <math.h>
#include <stdint.h>

#define NB 16384
#define ND_IN 512
#define NH 1024
#define NO 512
#define NE 8
#define NK 2

// output layout (fp32, flattened tuple)
#define RAW_OFF (NB * NO)
#define IDX_OFF (RAW_OFF + NB * NE)
#define ENT_OFF (IDX_OFF + NB * NK)

// ================= helpers =================
__device__ __forceinline__ uint32_t smem_to_u32(const void* p) {
    uint32_t a;
    asm("{ .reg .u64 t; cvta.to.shared.u64 t, %1; cvt.u32.u64 %0, t; }" : "=r"(a) : "l"(p));
    return a;
}
__device__ __forceinline__ void cp_async16(uint32_t dst, const void* src) {
    asm volatile("cp.async.cg.shared.global [%0], [%1], 16;" :: "r"(dst), "l"(src));
}
#define CP_COMMIT() asm volatile("cp.async.commit_group;" ::: "memory")
#define CP_WAIT1()  asm volatile("cp.async.wait_group 1;" ::: "memory")

__device__ __forceinline__ void ldmatrix4(uint32_t* r, uint32_t addr) {
    asm volatile("ldmatrix.sync.aligned.m8n8.x4.shared.b16 {%0,%1,%2,%3}, [%4];"
                 : "=r"(r[0]), "=r"(r[1]), "=r"(r[2]), "=r"(r[3]) : "r"(addr));
}
__device__ __forceinline__ void mma16816(float* c, const uint32_t* a, uint32_t b0, uint32_t b1) {
    asm volatile("mma.sync.aligned.m16n8k16.row.col.f32.f16.f16.f32 "
                 "{%0,%1,%2,%3}, {%4,%5,%6,%7}, {%8,%9}, {%0,%1,%2,%3};"
                 : "+f"(c[0]), "+f"(c[1]), "+f"(c[2]), "+f"(c[3])
                 : "r"(a[0]), "r"(a[1]), "r"(a[2]), "r"(a[3]), "r"(b0), "r"(b1));
}

// ================= scratch =================
__device__ int   g_counts[NE];
__device__ float g_entropy;
__device__ int   g_pair[NE * NB];
__device__ float g_pw[NE * NB];

__device__ __align__(16) __half g_xh[(size_t)NB * ND_IN];
__device__ __align__(16) __half g_xl[(size_t)NB * ND_IN];
__device__ __align__(16) __half g_w1h[(size_t)NE * NH * ND_IN];   // [e][n][k]
__device__ __align__(16) __half g_w2h[(size_t)NE * NO * NH];      // [e][o][k]
__device__ __align__(16) __half g_Hh[(size_t)NB * NK * NH];
__device__ __align__(16) __half g_Hl[(size_t)NB * NK * NH];
__device__ __align__(16) float  g_Y[(size_t)NB * NK * NO];

// ================= small kernels =================
__global__ void zero_kernel() {
    int t = threadIdx.x;
    if (t < NE) g_counts[t] = 0;
    if (t == 0) g_entropy = 0.0f;
}

// transpose + round: w[e][k][n] -> wh[e][n][k] (fp16)
template<int KD, int ND>
__global__ __launch_bounds__(256) void convert_w_kernel(
    const float* __restrict__ w, __half* __restrict__ wh)
{
    __shared__ float tile[32][33];
    int e = blockIdx.z;
    int n0 = blockIdx.x * 32;
    int k0 = blockIdx.y * 32;
    int tx = threadIdx.x & 31, ty = threadIdx.x >> 5;
    const float* we = w + (size_t)e * KD * ND;
#pragma unroll
    for (int ii = 0; ii < 4; ii++) {
        int k = ty + ii * 8;
        tile[k][tx] = we[(size_t)(k0 + k) * ND + n0 + tx];
    }
    __syncthreads();
#pragma unroll
    for (int ii = 0; ii < 4; ii++) {
        int n = ty + ii * 8;
        wh[((size_t)e * ND + n0 + n) * KD + k0 + tx] = __float2half_rn(tile[tx][n]);
    }
}

// ================= gating (+ fused x split) =================
__global__ __launch_bounds__(256) void gate_kernel(
    const float* __restrict__ x, const float* __restrict__ gw,
    const float* __restrict__ gb, float* __restrict__ out)
{
    __shared__ float gws[NE * ND_IN];
    __shared__ float gbs[NE];
    __shared__ float s_ent[8];

    int tid = threadIdx.x;
    for (int i = tid; i < NE * ND_IN; i += blockDim.x) {
        int e = i >> 9;
        int d = i & 511;
        gws[i] = gw[d * NE + e];
    }
    if (tid < NE) gbs[tid] = gb[tid];
    __syncthreads();

    int warp = tid >> 5, lane = tid & 31;
    int b = blockIdx.x * 8 + warp;

    float acc[NE];
#pragma unroll
    for (int e = 0; e < NE; e++) acc[e] = 0.0f;
    const float* xr = x + (size_t)b * ND_IN;
#pragma unroll 4
    for (int i = 0; i < 16; i++) {
        float xv = xr[lane + 32 * i];
        __half h = __float2half_rn(xv);
        __half l = __float2half_rn(xv - __half2float(h));
        g_xh[(size_t)b * ND_IN + lane + 32 * i] = h;
        g_xl[(size_t)b * ND_IN + lane + 32 * i] = l;
#pragma unroll
        for (int e = 0; e < NE; e++) acc[e] += xv * gws[e * ND_IN + lane + 32 * i];
    }
#pragma unroll
    for (int e = 0; e < NE; e++) {
#pragma unroll
        for (int off = 16; off > 0; off >>= 1)
            acc[e] += __shfl_xor_sync(0xffffffffu, acc[e], off);
    }

    if (lane == 0) {
        float raw[NE];
        float m = -1e30f;
#pragma unroll
        for (int e = 0; e < NE; e++) { raw[e] = acc[e] + gbs[e]; m = fmaxf(m, raw[e]); }
        float p[NE];
        float s = 0.0f;
#pragma unroll
        for (int e = 0; e < NE; e++) { p[e] = expf(raw[e] - m); s += p[e]; }
        float inv = 1.0f / s;
        float ent = 0.0f;
#pragma unroll
        for (int e = 0; e < NE; e++) {
            p[e] *= inv;
            ent -= p[e] * logf(p[e] + 1e-9f);
            out[RAW_OFF + (size_t)b * NE + e] = raw[e];
        }
        int i0 = 0;
#pragma unroll
        for (int e = 1; e < NE; e++) if (p[e] > p[i0]) i0 = e;
        int i1 = (i0 == 0) ? 1 : 0;
#pragma unroll
        for (int e = 0; e < NE; e++) if (e != i0 && e != i1 && p[e] > p[i1]) i1 = e;

        out[IDX_OFF + 2 * b + 0] = (float)i0;
        out[IDX_OFF + 2 * b + 1] = (float)i1;

        float v0 = p[i0], v1 = p[i1];
        float mm = fmaxf(v0, v1);
        float e0 = expf(v0 - mm), e1 = expf(v1 - mm);
        float iz = 1.0f / (e0 + e1);

        int pos0 = atomicAdd(&g_counts[i0], 1);
        g_pair[i0 * NB + pos0] = 2 * b;
        g_pw[i0 * NB + pos0]   = e0 * iz;
        int pos1 = atomicAdd(&g_counts[i1], 1);
        g_pair[i1 * NB + pos1] = 2 * b + 1;
        g_pw[i1 * NB + pos1]   = e1 * iz;

        s_ent[warp] = ent;
    }
    __syncthreads();
    if (tid == 0) {
        float t = 0.0f;
#pragma unroll
        for (int w = 0; w < 8; w++) t += s_ent[w];
        atomicAdd(&g_entropy, t);
    }
}

// ================= HMMA grouped gather GEMM =================
// 2-pass fp16 split of A; W rounded once. acc = A_hi@W + A_lo@W.
// MODE 0: H(fp16 hi/lo) = relu(x gather @ w1 + b1)   KD=512,  NDIM=1024
// MODE 1: Y(f32)        = w * (H gather @ w2 + b2)   KD=1024, NDIM=512
// CTA 128x128, 8 warps (warp tile 32x64, 4Mx2N), BK=32, 3-stage cp.async.

#define APITCH 80
#define TILE_BYTES (128 * APITCH)          // 10240  (one of Ah / Al / B)
#define STAGE_BYTES (3 * TILE_BYTES)       // 30720
#define HDR_BYTES 2048
#define SMEM_TOT (HDR_BYTES + 3 * STAGE_BYTES)   // 94208

template<int KD, int MODE>
__global__ __launch_bounds__(256, 2) void expert_gemm_mma(const float* __restrict__ bias_full)
{
    constexpr int NDIM = (MODE == 0) ? NH : NO;
    constexpr int RS   = (MODE == 0) ? ND_IN : NH;
    constexpr int NIT  = KD / 32;

    extern __shared__ char smem[];
    int*   s_pair = (int*)smem;
    float* s_w    = (float*)(smem + 512);
    float* s_bias = (float*)(smem + 1024);
    const uint32_t tilesU = smem_to_u32(smem + HDR_BYTES);

    const int e = blockIdx.z;
    const int n_e = g_counts[e];
    const int m0 = blockIdx.y * 128;
    if (m0 >= n_e) return;
    const int n0 = blockIdx.x * 128;
    const int tid = threadIdx.x;
    const int lane = tid & 31, wid = tid >> 5;

    if (tid < 128) {
        int gi = m0 + tid;
        if (gi < n_e) { s_pair[tid] = g_pair[e * NB + gi]; s_w[tid] = g_pw[e * NB + gi]; }
        else          { s_pair[tid] = -1;                  s_w[tid] = 0.0f; }
        s_bias[tid] = bias_full[(size_t)e * NDIM + n0 + tid];
    }
    __syncthreads();

    const __half* Ahp = (MODE == 0) ? g_xh : g_Hh;
    const __half* Alp = (MODE == 0) ? g_xl : g_Hl;
    const __half* Wp  = ((MODE == 0) ? g_w1h : g_w2h) + (size_t)e * NDIM * KD;

    // per-thread load slot: row = tid>>1 (0..127), 32B half = (tid&1)*32
    const int lrow = tid >> 1;
    const int lpart = (tid & 1) * 32;
    const int pp = s_pair[lrow];
    const size_t arow = (size_t)((pp < 0) ? 0 : ((MODE == 0) ? (pp >> 1) : pp));
    const char* aH = (const char*)(Ahp + arow * RS) + lpart;
    const char* aL = (const char*)(Alp + arow * RS) + lpart;
    const char* bW = (const char*)(Wp + (size_t)(n0 + lrow) * KD) + lpart;
    const uint32_t rowDst = (uint32_t)lrow * APITCH + lpart;

    auto load_stage = [&](int it) {
        const uint32_t db = tilesU + (uint32_t)(it % 3) * STAGE_BYTES;
        const size_t ko = (size_t)it * 64;
#pragma unroll
        for (int j = 0; j < 2; j++) {
            cp_async16(db + rowDst + j * 16,                  aH + ko + j * 16);
            cp_async16(db + TILE_BYTES + rowDst + j * 16,     aL + ko + j * 16);
            cp_async16(db + 2 * TILE_BYTES + rowDst + j * 16, bW + ko + j * 16);
        }
    };

    float acc[2][8][4];
#pragma unroll
    for (int mi = 0; mi < 2; mi++)
#pragma unroll
        for (int ni = 0; ni < 8; ni++)
#pragma unroll
            for (int q = 0; q < 4; q++) acc[mi][ni][q] = 0.0f;

    const int wm0 = (wid & 3) * 32;
    const int wn0 = (wid >> 2) * 64;
    const int aRow = (lane & 15);
    const int aChk = (lane >> 4);
    const int bRow = ((lane >> 4) << 3) + (lane & 7);
    const int bChk = ((lane >> 3) & 1);

    load_stage(0); CP_COMMIT();
    load_stage(1); CP_COMMIT();

    for (int it = 0; it < NIT; it++) {
        CP_WAIT1();
        __syncthreads();
        if (it + 2 < NIT) load_stage(it + 2);
        CP_COMMIT();

        const uint32_t st = tilesU + (uint32_t)(it % 3) * STAGE_BYTES;
#pragma unroll
        for (int s = 0; s < 2; s++) {
            uint32_t b[4][4];
#pragma unroll
            for (int q = 0; q < 4; q++)
                ldmatrix4(b[q], st + 2 * TILE_BYTES
                          + (uint32_t)(wn0 + q * 16 + bRow) * APITCH + (2 * s + bChk) * 16);
            uint32_t a[2][4];
#pragma unroll
            for (int mi = 0; mi < 2; mi++)
                ldmatrix4(a[mi], st
                          + (uint32_t)(wm0 + mi * 16 + aRow) * APITCH + (2 * s + aChk) * 16);
#pragma unroll
            for (int mi = 0; mi < 2; mi++)
#pragma unroll
                for (int q = 0; q < 4; q++) {
                    mma16816(acc[mi][2 * q],     a[mi], b[q][0], b[q][1]);
                    mma16816(acc[mi][2 * q + 1], a[mi], b[q][2], b[q][3]);
                }
#pragma unroll
            for (int mi = 0; mi < 2; mi++)
                ldmatrix4(a[mi], st + TILE_BYTES
                          + (uint32_t)(wm0 + mi * 16 + aRow) * APITCH + (2 * s + aChk) * 16);
#pragma unroll
            for (int mi = 0; mi < 2; mi++)
#pragma unroll
                for (int q = 0; q < 4; q++) {
                    mma16816(acc[mi][2 * q],     a[mi], b[q][0], b[q][1]);
                    mma16816(acc[mi][2 * q + 1], a[mi], b[q][2], b[q][3]);
                }
        }
    }

    // ================= epilogue =================
#pragma unroll
    for (int mi = 0; mi < 2; mi++) {
#pragma unroll
        for (int half = 0; half < 2; half++) {
            const int rloc = wm0 + mi * 16 + (lane >> 2) + half * 8;
            const int p = s_pair[rloc];
            if (p < 0) continue;
            const float wt = s_w[rloc];
#pragma unroll
            for (int ni = 0; ni < 8; ni++) {
                const int col = wn0 + ni * 8 + 2 * (lane & 3);
                float v0 = acc[mi][ni][2 * half]     + s_bias[col];
                float v1 = acc[mi][ni][2 * half + 1] + s_bias[col + 1];
                if (MODE == 0) {
                    v0 = fmaxf(v0, 0.0f);
                    v1 = fmaxf(v1, 0.0f);
                    __half2 h = __floats2half2_rn(v0, v1);
                    float r0 = v0 - __half2float(h.x);
                    float r1 = v1 - __half2float(h.y);
                    __half2 l = __floats2half2_rn(r0, r1);
                    *(__half2*)(g_Hh + (size_t)p * NH + n0 + col) = h;
                    *(__half2*)(g_Hl + (size_t)p * NH + n0 + col) = l;
                } else {
                    *(float2*)(g_Y + (size_t)p * NO + n0 + col) = make_float2(v0 * wt, v1 * wt);
                }
            }
        }
    }
}

// ================= combine =================
__global__ __launch_bounds__(256) void combine_kernel(float* __restrict__ out)
{
    const float4* Y4 = (const float4*)g_Y;
    float4* out4 = (float4*)out;
    int i4 = blockIdx.x * blockDim.x + threadIdx.x;
    int olin = i4 * 4;
    int b = olin >> 9;
    int o4 = (olin & 511) >> 2;
    float4 a = Y4[(size_t)b * 256 + o4];
    float4 c = Y4[(size_t)b * 256 + 128 + o4];
    out4[i4] = make_float4(a.x + c.x, a.y + c.y, a.z + c.z, a.w + c.w);
    if (i4 == 0) out[ENT_OFF] = g_entropy * (1.0f / (float)NB);
}

// ================= host =================
extern "C" void kernel_launch(void* const* d_in, const int* in_sizes, int n_in,
                              void* d_out, int out_size)
{
    const float* x  = (const float*)d_in[0];
    const float* gw = (const float*)d_in[1];
    const float* gb = (const float*)d_in[2];
    const float* w1 = (const float*)d_in[3];
    const float* b1 = (const float*)d_in[4];
    const float* w2 = (const float*)d_in[5];
    const float* b2 = (const float*)d_in[6];
    float* out = (float*)d_out;

    __half *w1h, *w2h;
    cudaGetSymbolAddress((void**)&w1h, g_w1h);
    cudaGetSymbolAddress((void**)&w2h, g_w2h);

    cudaFuncSetAttribute(expert_gemm_mma<ND_IN, 0>, cudaFuncAttributeMaxDynamicSharedMemorySize, SMEM_TOT);
    cudaFuncSetAttribute(expert_gemm_mma<NH, 1>,    cudaFuncAttributeMaxDynamicSharedMemorySize, SMEM_TOT);

    // order chosen so launch idx 3 = gemmA, idx 5 = gemmB (single-launch ncu capture)
    zero_kernel<<<1, 32>>>();                                                   // 0
    gate_kernel<<<NB / 8, 256>>>(x, gw, gb, out);                               // 1
    convert_w_kernel<ND_IN, NH><<<dim3(NH / 32, ND_IN / 32, NE), 256>>>(w1, w1h); // 2
    expert_gemm_mma<ND_IN, 0><<<dim3(NH / 128, 128, NE), 256, SMEM_TOT>>>(b1);  // 3
    convert_w_kernel<NH, NO><<<dim3(NO / 32, NH / 32, NE), 256>>>(w2, w2h);     // 4
    expert_gemm_mma<NH, 1><<<dim3(NO / 128, 128, NE), 256, SMEM_TOT>>>(b2);     // 5
    combine_kernel<<<(NB * NO / 4) / 256, 256>>>(out);                          // 6
}

// round 6
// speedup vs baseline: 4.7691x; 1.5730x over previous
#include <cuda_runtime.h>
#include <cuda_bf16.h>
#include <cuda_fp16.h>
#include <math.h>
#include <stdint.h>

#define NB 16384
#define ND_IN 512
#define NH 1024
#define NO 512
#define NE 8
#define NK 2

// output layout (fp32, flattened tuple)
#define RAW_OFF (NB * NO)
#define IDX_OFF (RAW_OFF + NB * NE)
#define ENT_OFF (IDX_OFF + NB * NK)

// ================= helpers =================
__device__ __forceinline__ uint32_t smem_to_u32(const void* p) {
    uint32_t a;
    asm("{ .reg .u64 t; cvta.to.shared.u64 t, %1; cvt.u32.u64 %0, t; }" : "=r"(a) : "l"(p));
    return a;
}
__device__ __forceinline__ void cp_async16(uint32_t dst, const void* src) {
    asm volatile("cp.async.cg.shared.global [%0], [%1], 16;" :: "r"(dst), "l"(src));
}
#define CP_COMMIT() asm volatile("cp.async.commit_group;" ::: "memory")
#define CP_WAIT2()  asm volatile("cp.async.wait_group 2;" ::: "memory")

__device__ __forceinline__ void ldmatrix4(uint32_t* r, uint32_t addr) {
    asm volatile("ldmatrix.sync.aligned.m8n8.x4.shared.b16 {%0,%1,%2,%3}, [%4];"
                 : "=r"(r[0]), "=r"(r[1]), "=r"(r[2]), "=r"(r[3]) : "r"(addr));
}
__device__ __forceinline__ void mma16816(float* c, const uint32_t* a, uint32_t b0, uint32_t b1) {
    asm volatile("mma.sync.aligned.m16n8k16.row.col.f32.f16.f16.f32 "
                 "{%0,%1,%2,%3}, {%4,%5,%6,%7}, {%8,%9}, {%0,%1,%2,%3};"
                 : "+f"(c[0]), "+f"(c[1]), "+f"(c[2]), "+f"(c[3])
                 : "r"(a[0]), "r"(a[1]), "r"(a[2]), "r"(a[3]), "r"(b0), "r"(b1));
}

// ================= scratch =================
__device__ int   g_counts[NE];
__device__ float g_entropy;
__device__ int   g_pair[NE * NB];
__device__ float g_pw[NE * NB];

__device__ __align__(16) __half g_xh[(size_t)NB * ND_IN];
__device__ __align__(16) __half g_w1h[(size_t)NE * NH * ND_IN];   // [e][n][k]
__device__ __align__(16) __half g_w2h[(size_t)NE * NO * NH];      // [e][o][k]
__device__ __align__(16) __half g_Hh[(size_t)NB * NK * NH];
__device__ __align__(16) float  g_Y[(size_t)NB * NK * NO];

// ================= small kernels =================
__global__ void zero_kernel() {
    int t = threadIdx.x;
    if (t < NE) g_counts[t] = 0;
    if (t == 0) g_entropy = 0.0f;
}

// transpose + round: w[e][k][n] -> wh[e][n][k] (fp16)
template<int KD, int ND>
__global__ __launch_bounds__(256) void convert_w_kernel(
    const float* __restrict__ w, __half* __restrict__ wh)
{
    __shared__ float tile[32][33];
    int e = blockIdx.z;
    int n0 = blockIdx.x * 32;
    int k0 = blockIdx.y * 32;
    int tx = threadIdx.x & 31, ty = threadIdx.x >> 5;
    const float* we = w + (size_t)e * KD * ND;
#pragma unroll
    for (int ii = 0; ii < 4; ii++) {
        int k = ty + ii * 8;
        tile[k][tx] = we[(size_t)(k0 + k) * ND + n0 + tx];
    }
    __syncthreads();
#pragma unroll
    for (int ii = 0; ii < 4; ii++) {
        int n = ty + ii * 8;
        wh[((size_t)e * ND + n0 + n) * KD + k0 + tx] = __float2half_rn(tile[tx][n]);
    }
}

// ================= gating (+ fused x round to fp16) =================
__global__ __launch_bounds__(256) void gate_kernel(
    const float* __restrict__ x, const float* __restrict__ gw,
    const float* __restrict__ gb, float* __restrict__ out)
{
    __shared__ float gws[NE * ND_IN];
    __shared__ float gbs[NE];
    __shared__ float s_ent[8];

    int tid = threadIdx.x;
    for (int i = tid; i < NE * ND_IN; i += blockDim.x) {
        int e = i >> 9;
        int d = i & 511;
        gws[i] = gw[d * NE + e];
    }
    if (tid < NE) gbs[tid] = gb[tid];
    __syncthreads();

    int warp = tid >> 5, lane = tid & 31;
    int b = blockIdx.x * 8 + warp;

    float acc[NE];
#pragma unroll
    for (int e = 0; e < NE; e++) acc[e] = 0.0f;
    const float* xr = x + (size_t)b * ND_IN;
#pragma unroll 4
    for (int i = 0; i < 16; i++) {
        float xv = xr[lane + 32 * i];
        g_xh[(size_t)b * ND_IN + lane + 32 * i] = __float2half_rn(xv);
#pragma unroll
        for (int e = 0; e < NE; e++) acc[e] += xv * gws[e * ND_IN + lane + 32 * i];
    }
#pragma unroll
    for (int e = 0; e < NE; e++) {
#pragma unroll
        for (int off = 16; off > 0; off >>= 1)
            acc[e] += __shfl_xor_sync(0xffffffffu, acc[e], off);
    }

    if (lane == 0) {
        float raw[NE];
        float m = -1e30f;
#pragma unroll
        for (int e = 0; e < NE; e++) { raw[e] = acc[e] + gbs[e]; m = fmaxf(m, raw[e]); }
        float p[NE];
        float s = 0.0f;
#pragma unroll
        for (int e = 0; e < NE; e++) { p[e] = expf(raw[e] - m); s += p[e]; }
        float inv = 1.0f / s;
        float ent = 0.0f;
#pragma unroll
        for (int e = 0; e < NE; e++) {
            p[e] *= inv;
            ent -= p[e] * logf(p[e] + 1e-9f);
            out[RAW_OFF + (size_t)b * NE + e] = raw[e];
        }
        int i0 = 0;
#pragma unroll
        for (int e = 1; e < NE; e++) if (p[e] > p[i0]) i0 = e;
        int i1 = (i0 == 0) ? 1 : 0;
#pragma unroll
        for (int e = 0; e < NE; e++) if (e != i0 && e != i1 && p[e] > p[i1]) i1 = e;

        out[IDX_OFF + 2 * b + 0] = (float)i0;
        out[IDX_OFF + 2 * b + 1] = (float)i1;

        float v0 = p[i0], v1 = p[i1];
        float mm = fmaxf(v0, v1);
        float e0 = expf(v0 - mm), e1 = expf(v1 - mm);
        float iz = 1.0f / (e0 + e1);

        int pos0 = atomicAdd(&g_counts[i0], 1);
        g_pair[i0 * NB + pos0] = 2 * b;
        g_pw[i0 * NB + pos0]   = e0 * iz;
        int pos1 = atomicAdd(&g_counts[i1], 1);
        g_pair[i1 * NB + pos1] = 2 * b + 1;
        g_pw[i1 * NB + pos1]   = e1 * iz;

        s_ent[warp] = ent;
    }
    __syncthreads();
    if (tid == 0) {
        float t = 0.0f;
#pragma unroll
        for (int w = 0; w < 8; w++) t += s_ent[w];
        atomicAdd(&g_entropy, t);
    }
}

// ================= HMMA grouped gather GEMM (1-pass fp16) =================
// MODE 0: H(fp16) = relu(x gather @ w1 + b1)   KD=512,  NDIM=1024
// MODE 1: Y(f32)  = w * (H gather @ w2 + b2)   KD=1024, NDIM=512
// CTA 128x128, 8 warps (warp tile 32x64, 4Mx2N), BK=32, 4-stage cp.async.

#define APITCH 80
#define TILE_BYTES (128 * APITCH)          // 10240
#define STAGE_BYTES (2 * TILE_BYTES)       // 20480  (A tile + B tile)
#define NSTG 4
#define HDR_BYTES 2048
#define SMEM_TOT (HDR_BYTES + NSTG * STAGE_BYTES)   // 83968

template<int KD, int MODE>
__global__ __launch_bounds__(256, 2) void expert_gemm_mma(const float* __restrict__ bias_full)
{
    constexpr int NDIM = (MODE == 0) ? NH : NO;
    constexpr int RS   = (MODE == 0) ? ND_IN : NH;
    constexpr int NIT  = KD / 32;

    extern __shared__ char smem[];
    int*   s_pair = (int*)smem;
    float* s_w    = (float*)(smem + 512);
    float* s_bias = (float*)(smem + 1024);
    const uint32_t tilesU = smem_to_u32(smem + HDR_BYTES);

    const int e = blockIdx.z;
    const int n_e = g_counts[e];
    const int m0 = blockIdx.y * 128;
    if (m0 >= n_e) return;
    const int n0 = blockIdx.x * 128;
    const int tid = threadIdx.x;
    const int lane = tid & 31, wid = tid >> 5;

    if (tid < 128) {
        int gi = m0 + tid;
        if (gi < n_e) { s_pair[tid] = g_pair[e * NB + gi]; s_w[tid] = g_pw[e * NB + gi]; }
        else          { s_pair[tid] = -1;                  s_w[tid] = 0.0f; }
        s_bias[tid] = bias_full[(size_t)e * NDIM + n0 + tid];
    }
    __syncthreads();

    const __half* Ahp = (MODE == 0) ? g_xh : g_Hh;
    const __half* Wp  = ((MODE == 0) ? g_w1h : g_w2h) + (size_t)e * NDIM * KD;

    // per-thread load slot: row = tid>>1 (0..127), 32B half = (tid&1)*32
    const int lrow = tid >> 1;
    const int lpart = (tid & 1) * 32;
    const int pp = s_pair[lrow];
    const size_t arow = (size_t)((pp < 0) ? 0 : ((MODE == 0) ? (pp >> 1) : pp));
    const char* aH = (const char*)(Ahp + arow * RS) + lpart;
    const char* bW = (const char*)(Wp + (size_t)(n0 + lrow) * KD) + lpart;
    const uint32_t rowDst = (uint32_t)lrow * APITCH + lpart;

    auto load_stage = [&](int it) {
        const uint32_t db = tilesU + (uint32_t)(it % NSTG) * STAGE_BYTES;
        const size_t ko = (size_t)it * 64;
#pragma unroll
        for (int j = 0; j < 2; j++) {
            cp_async16(db + rowDst + j * 16,              aH + ko + j * 16);
            cp_async16(db + TILE_BYTES + rowDst + j * 16, bW + ko + j * 16);
        }
    };

    float acc[2][8][4];
#pragma unroll
    for (int mi = 0; mi < 2; mi++)
#pragma unroll
        for (int ni = 0; ni < 8; ni++)
#pragma unroll
            for (int q = 0; q < 4; q++) acc[mi][ni][q] = 0.0f;

    const int wm0 = (wid & 3) * 32;
    const int wn0 = (wid >> 2) * 64;
    const int aRow = (lane & 15);
    const int aChk = (lane >> 4);
    const int bRow = ((lane >> 4) << 3) + (lane & 7);
    const int bChk = ((lane >> 3) & 1);

    load_stage(0); CP_COMMIT();
    load_stage(1); CP_COMMIT();
    load_stage(2); CP_COMMIT();

    for (int it = 0; it < NIT; it++) {
        CP_WAIT2();
        __syncthreads();
        if (it + 3 < NIT) load_stage(it + 3);
        CP_COMMIT();

        const uint32_t st = tilesU + (uint32_t)(it % NSTG) * STAGE_BYTES;
#pragma unroll
        for (int s = 0; s < 2; s++) {
            uint32_t b[4][4];
#pragma unroll
            for (int q = 0; q < 4; q++)
                ldmatrix4(b[q], st + TILE_BYTES
                          + (uint32_t)(wn0 + q * 16 + bRow) * APITCH + (2 * s + bChk) * 16);
            uint32_t a[2][4];
#pragma unroll
            for (int mi = 0; mi < 2; mi++)
                ldmatrix4(a[mi], st
                          + (uint32_t)(wm0 + mi * 16 + aRow) * APITCH + (2 * s + aChk) * 16);
#pragma unroll
            for (int mi = 0; mi < 2; mi++)
#pragma unroll
                for (int q = 0; q < 4; q++) {
                    mma16816(acc[mi][2 * q],     a[mi], b[q][0], b[q][1]);
                    mma16816(acc[mi][2 * q + 1], a[mi], b[q][2], b[q][3]);
                }
        }
    }

    // ================= epilogue =================
#pragma unroll
    for (int mi = 0; mi < 2; mi++) {
#pragma unroll
        for (int half = 0; half < 2; half++) {
            const int rloc = wm0 + mi * 16 + (lane >> 2) + half * 8;
            const int p = s_pair[rloc];
            if (p < 0) continue;
            const float wt = s_w[rloc];
#pragma unroll
            for (int ni = 0; ni < 8; ni++) {
                const int col = wn0 + ni * 8 + 2 * (lane & 3);
                float v0 = acc[mi][ni][2 * half]     + s_bias[col];
                float v1 = acc[mi][ni][2 * half + 1] + s_bias[col + 1];
                if (MODE == 0) {
                    v0 = fmaxf(v0, 0.0f);
                    v1 = fmaxf(v1, 0.0f);
                    *(__half2*)(g_Hh + (size_t)p * NH + n0 + col) = __floats2half2_rn(v0, v1);
                } else {
                    *(float2*)(g_Y + (size_t)p * NO + n0 + col) = make_float2(v0 * wt, v1 * wt);
                }
            }
        }
    }
}

// ================= combine =================
__global__ __launch_bounds__(256) void combine_kernel(float* __restrict__ out)
{
    const float4* Y4 = (const float4*)g_Y;
    float4* out4 = (float4*)out;
    int i4 = blockIdx.x * blockDim.x + threadIdx.x;
    int olin = i4 * 4;
    int b = olin >> 9;
    int o4 = (olin & 511) >> 2;
    float4 a = Y4[(size_t)b * 256 + o4];
    float4 c = Y4[(size_t)b * 256 + 128 + o4];
    out4[i4] = make_float4(a.x + c.x, a.y + c.y, a.z + c.z, a.w + c.w);
    if (i4 == 0) out[ENT_OFF] = g_entropy * (1.0f / (float)NB);
}

// ================= host =================
extern "C" void kernel_launch(void* const* d_in, const int* in_sizes, int n_in,
                              void* d_out, int out_size)
{
    const float* x  = (const float*)d_in[0];
    const float* gw = (const float*)d_in[1];
    const float* gb = (const float*)d_in[2];
    const float* w1 = (const float*)d_in[3];
    const float* b1 = (const float*)d_in[4];
    const float* w2 = (const float*)d_in[5];
    const float* b2 = (const float*)d_in[6];
    float* out = (float*)d_out;

    __half *w1h, *w2h;
    cudaGetSymbolAddress((void**)&w1h, g_w1h);
    cudaGetSymbolAddress((void**)&w2h, g_w2h);

    cudaFuncSetAttribute(expert_gemm_mma<ND_IN, 0>, cudaFuncAttributeMaxDynamicSharedMemorySize, SMEM_TOT);
    cudaFuncSetAttribute(expert_gemm_mma<NH, 1>,    cudaFuncAttributeMaxDynamicSharedMemorySize, SMEM_TOT);

    // order chosen so launch idx 3 = gemmA, idx 5 = gemmB (single-launch ncu capture)
    zero_kernel<<<1, 32>>>();                                                   // 0
    gate_kernel<<<NB / 8, 256>>>(x, gw, gb, out);                               // 1
    convert_w_kernel<ND_IN, NH><<<dim3(NH / 32, ND_IN / 32, NE), 256>>>(w1, w1h); // 2
    expert_gemm_mma<ND_IN, 0><<<dim3(NH / 128, 128, NE), 256, SMEM_TOT>>>(b1);  // 3
    convert_w_kernel<NH, NO><<<dim3(NO / 32, NH / 32, NE), 256>>>(w2, w2h);     // 4
    expert_gemm_mma<NH, 1><<<dim3(NO / 128, 128, NE), 256, SMEM_TOT>>>(b2);     // 5
    combine_kernel<<<(NB * NO / 4) / 256, 256>>>(out);                          // 6
}